// round 1
// baseline (speedup 1.0000x reference)
#include <cuda_runtime.h>
#include <cuda_bf16.h>
#include <math.h>

// Problem constants
#define BATCH 2
#define SEQ   2048
#define DIM   1024
#define HEADS 16
#define DKV   64
#define MROWS (BATCH*SEQ)          // 4096
#define OUT_ELEMS   ((size_t)MROWS*DIM)            // 4194304
#define PB_ELEMS    ((size_t)HEADS*SEQ*SEQ)        // 67108864
#define BIAS_TBL_N  (HEADS*4095)                   // 65520

// Scratch (device globals, no runtime allocation)
__device__ float g_q[MROWS*DIM];
__device__ float g_k[MROWS*DIM];
__device__ float g_v[MROWS*DIM];
__device__ float g_attn[MROWS*DIM];
__device__ float g_bias_tbl[BIAS_TBL_N];

// ---------------------------------------------------------------------------
// Relative-position bias table: bias[h][rel + 2047], rel = k - q
// ---------------------------------------------------------------------------
__global__ void bias_table_kernel(const float* __restrict__ rel_table,
                                  float* __restrict__ bias)
{
    int i = blockIdx.x * blockDim.x + threadIdx.x;
    if (i >= BIAS_TBL_N) return;
    int h   = i / 4095;
    int rel = (i % 4095) - 2047;       // rel = k - q
    int n   = -rel;                    // q - k
    int ret = 0;
    if (n < 0) { ret = 16; n = -n; }
    int val;
    if (n < 8) {
        val = n;
    } else {
        // (log(n/8) / log(16)) * 8, fp32, truncated toward zero.
        float t = (logf((float)n / 8.0f) / 2.772588722239781f) * 8.0f;
        int it = (int)t;
        // snap: exact power-of-two boundaries (n=16,32,64,128) evaluate to
        // exact integers in correctly-rounded fp32; protect against a 1-ulp
        // downward excursion (real-math margin elsewhere is > 0.015).
        if (t - (float)it > 0.99995f) it += 1;
        val = 8 + it;
        if (val > 15) val = 15;
    }
    bias[i] = rel_table[(val + ret) * HEADS + h];
}

// ---------------------------------------------------------------------------
// Broadcast bias table into the position_bias output [H][S][S]
// ---------------------------------------------------------------------------
__global__ __launch_bounds__(256) void pb_out_kernel(const float* __restrict__ bias,
                                                     float* __restrict__ pb)
{
    size_t i = ((size_t)blockIdx.x * blockDim.x + threadIdx.x) * 4;
    int k = (int)(i & 2047);
    int q = (int)((i >> 11) & 2047);
    int h = (int)(i >> 22);
    const float* src = bias + h * 4095 + 2047 - q + k;
    float4 v = make_float4(src[0], src[1], src[2], src[3]);
    *(float4*)(pb + i) = v;
}

// ---------------------------------------------------------------------------
// Tiled fp32 GEMM: C[M,N] = A[M,K] @ B[K,N].  BM=128, BN=64, BK=16, 256 thr.
// ---------------------------------------------------------------------------
__global__ __launch_bounds__(256) void gemm_kernel(const float* __restrict__ A,
                                                   const float* __restrict__ B,
                                                   float* __restrict__ C,
                                                   int M, int N, int K)
{
    __shared__ float As[16][132];   // A transposed: As[k][m], padded
    __shared__ float Bs[16][64];

    const int tid = threadIdx.x;
    const int tx  = tid & 15;       // 0..15 -> 4 cols each
    const int ty  = tid >> 4;       // 0..15 -> 8 rows each
    const int m0  = blockIdx.y * 128;
    const int n0  = blockIdx.x * 64;

    float acc[8][4];
#pragma unroll
    for (int i = 0; i < 8; i++)
#pragma unroll
        for (int j = 0; j < 4; j++) acc[i][j] = 0.f;

    const int la_r = tid >> 2;            // 0..63
    const int la_c = (tid & 3) << 2;      // 0,4,8,12
    const int lb_k = tid >> 4;            // 0..15
    const int lb_n = (tid & 15) << 2;     // 0..60

    const float* Ap = A + (size_t)(m0 + la_r) * K + la_c;
    const float* Bp = B + (size_t)lb_k * N + n0 + lb_n;

    for (int kc = 0; kc < K; kc += 16) {
        float4 a0 = *(const float4*)Ap;
        float4 a1 = *(const float4*)(Ap + (size_t)64 * K);
        float4 b0 = *(const float4*)Bp;
        __syncthreads();   // previous tile's compute done before overwrite
        As[la_c + 0][la_r]      = a0.x;
        As[la_c + 1][la_r]      = a0.y;
        As[la_c + 2][la_r]      = a0.z;
        As[la_c + 3][la_r]      = a0.w;
        As[la_c + 0][la_r + 64] = a1.x;
        As[la_c + 1][la_r + 64] = a1.y;
        As[la_c + 2][la_r + 64] = a1.z;
        As[la_c + 3][la_r + 64] = a1.w;
        *(float4*)&Bs[lb_k][lb_n] = b0;
        __syncthreads();
        Ap += 16;
        Bp += (size_t)16 * N;

#pragma unroll
        for (int kk = 0; kk < 16; kk++) {
            float4 x0 = *(const float4*)&As[kk][ty * 8];
            float4 x1 = *(const float4*)&As[kk][ty * 8 + 4];
            float4 y  = *(const float4*)&Bs[kk][tx * 4];
            float xa[8] = {x0.x, x0.y, x0.z, x0.w, x1.x, x1.y, x1.z, x1.w};
            float yb[4] = {y.x, y.y, y.z, y.w};
#pragma unroll
            for (int i = 0; i < 8; i++)
#pragma unroll
                for (int j = 0; j < 4; j++)
                    acc[i][j] += xa[i] * yb[j];
        }
    }

#pragma unroll
    for (int i = 0; i < 8; i++) {
        float4 w = make_float4(acc[i][0], acc[i][1], acc[i][2], acc[i][3]);
        *(float4*)&C[(size_t)(m0 + ty * 8 + i) * N + n0 + tx * 4] = w;
    }
}

// ---------------------------------------------------------------------------
// Flash attention: one block = (q-tile of 64, head, batch). 256 threads.
// Smem: Qs[64][65], Ks[64][65], Ss[64][65], Vs[64][64], msk[64]
// ---------------------------------------------------------------------------
#define ATTN_SMEM_FLOATS (3 * 64 * 65 + 64 * 64 + 64)
#define ATTN_SMEM_BYTES  (ATTN_SMEM_FLOATS * 4)

__global__ __launch_bounds__(256) void attn_kernel(const float* __restrict__ Q,
                                                   const float* __restrict__ K,
                                                   const float* __restrict__ V,
                                                   const float* __restrict__ mask,
                                                   const float* __restrict__ bias,
                                                   float* __restrict__ O)
{
    extern __shared__ float sm[];
    float* Qs  = sm;                   // 64*65
    float* Ks  = Qs + 64 * 65;         // 64*65
    float* Ss  = Ks + 64 * 65;         // 64*65
    float* Vs  = Ss + 64 * 65;         // 64*64
    float* msk = Vs + 64 * 64;         // 64

    const int tid = threadIdx.x;
    const int b   = blockIdx.z;
    const int h   = blockIdx.y;
    const int q0  = blockIdx.x * 64;

    // load Q tile
    const float* Qb = Q + ((size_t)(b * SEQ + q0)) * DIM + h * DKV;
    for (int i = tid; i < 64 * 64; i += 256) {
        int r = i >> 6, c = i & 63;
        Qs[r * 65 + c] = Qb[(size_t)r * DIM + c];
    }

    const int tx = tid & 15, ty = tid >> 4;   // phase A layout (16x16, 4x4 each)
    const int rr = tid >> 2;                  // softmax row (quad of 4 threads)
    const int d0 = (tid & 3) * 16;            // this thread's 16 value dims

    float m_i = -INFINITY;
    float l_i = 0.f;
    float o[16];
#pragma unroll
    for (int j = 0; j < 16; j++) o[j] = 0.f;

    const float* gb = bias + h * 4095 + 2047 - q0;  // gb[k0+kc - qr]

    for (int k0 = 0; k0 < SEQ; k0 += 64) {
        __syncthreads();
        const float* Kb = K + ((size_t)(b * SEQ + k0)) * DIM + h * DKV;
        const float* Vb = V + ((size_t)(b * SEQ + k0)) * DIM + h * DKV;
        for (int i = tid; i < 64 * 64; i += 256) {
            int r = i >> 6, c = i & 63;
            Ks[r * 65 + c] = Kb[(size_t)r * DIM + c];
            Vs[r * 64 + c] = Vb[(size_t)r * DIM + c];
        }
        if (tid < 64) msk[tid] = mask[b * SEQ + k0 + tid];
        __syncthreads();

        // ---- Phase A: S = Q K^T (+bias +mask) ----
        float acc[4][4];
#pragma unroll
        for (int i = 0; i < 4; i++)
#pragma unroll
            for (int j = 0; j < 4; j++) acc[i][j] = 0.f;

#pragma unroll 4
        for (int d = 0; d < 64; d++) {
            float a0 = Qs[(ty * 4 + 0) * 65 + d];
            float a1 = Qs[(ty * 4 + 1) * 65 + d];
            float a2 = Qs[(ty * 4 + 2) * 65 + d];
            float a3 = Qs[(ty * 4 + 3) * 65 + d];
            float b0 = Ks[(tx * 4 + 0) * 65 + d];
            float b1 = Ks[(tx * 4 + 1) * 65 + d];
            float b2 = Ks[(tx * 4 + 2) * 65 + d];
            float b3 = Ks[(tx * 4 + 3) * 65 + d];
            acc[0][0] += a0 * b0; acc[0][1] += a0 * b1; acc[0][2] += a0 * b2; acc[0][3] += a0 * b3;
            acc[1][0] += a1 * b0; acc[1][1] += a1 * b1; acc[1][2] += a1 * b2; acc[1][3] += a1 * b3;
            acc[2][0] += a2 * b0; acc[2][1] += a2 * b1; acc[2][2] += a2 * b2; acc[2][3] += a2 * b3;
            acc[3][0] += a3 * b0; acc[3][1] += a3 * b1; acc[3][2] += a3 * b2; acc[3][3] += a3 * b3;
        }
#pragma unroll
        for (int i = 0; i < 4; i++) {
            int qr = ty * 4 + i;
#pragma unroll
            for (int j = 0; j < 4; j++) {
                int kc = tx * 4 + j;
                Ss[qr * 65 + kc] = acc[i][j] + __ldg(gb + k0 + kc - qr) + msk[kc];
            }
        }
        __syncthreads();

        // ---- Phase B: online softmax (quad per row) ----
        float pm = -INFINITY;
#pragma unroll
        for (int mI = 0; mI < 16; mI++)
            pm = fmaxf(pm, Ss[rr * 65 + d0 + mI]);
        pm = fmaxf(pm, __shfl_xor_sync(0xffffffffu, pm, 1));
        pm = fmaxf(pm, __shfl_xor_sync(0xffffffffu, pm, 2));
        float mnew = fmaxf(m_i, pm);
        float corr = __expf(m_i - mnew);
        float psum = 0.f;
#pragma unroll
        for (int mI = 0; mI < 16; mI++) {
            float p = __expf(Ss[rr * 65 + d0 + mI] - mnew);
            Ss[rr * 65 + d0 + mI] = p;
            psum += p;
        }
        psum += __shfl_xor_sync(0xffffffffu, psum, 1);
        psum += __shfl_xor_sync(0xffffffffu, psum, 2);
        l_i = l_i * corr + psum;
        m_i = mnew;
#pragma unroll
        for (int j = 0; j < 16; j++) o[j] *= corr;
        __syncwarp();

        // ---- Phase C: O += P V ----
#pragma unroll 4
        for (int kk = 0; kk < 64; kk++) {
            float p = Ss[rr * 65 + kk];
            float4 v0 = *(const float4*)&Vs[kk * 64 + d0];
            float4 v1 = *(const float4*)&Vs[kk * 64 + d0 + 4];
            float4 v2 = *(const float4*)&Vs[kk * 64 + d0 + 8];
            float4 v3 = *(const float4*)&Vs[kk * 64 + d0 + 12];
            o[0]  += p * v0.x; o[1]  += p * v0.y; o[2]  += p * v0.z; o[3]  += p * v0.w;
            o[4]  += p * v1.x; o[5]  += p * v1.y; o[6]  += p * v1.z; o[7]  += p * v1.w;
            o[8]  += p * v2.x; o[9]  += p * v2.y; o[10] += p * v2.z; o[11] += p * v2.w;
            o[12] += p * v3.x; o[13] += p * v3.y; o[14] += p * v3.z; o[15] += p * v3.w;
        }
    }

    float inv = 1.0f / l_i;
    float* Ob = O + ((size_t)(b * SEQ + q0 + rr)) * DIM + h * DKV + d0;
    float4 w0 = make_float4(o[0] * inv,  o[1] * inv,  o[2] * inv,  o[3] * inv);
    float4 w1 = make_float4(o[4] * inv,  o[5] * inv,  o[6] * inv,  o[7] * inv);
    float4 w2 = make_float4(o[8] * inv,  o[9] * inv,  o[10] * inv, o[11] * inv);
    float4 w3 = make_float4(o[12] * inv, o[13] * inv, o[14] * inv, o[15] * inv);
    ((float4*)Ob)[0] = w0;
    ((float4*)Ob)[1] = w1;
    ((float4*)Ob)[2] = w2;
    ((float4*)Ob)[3] = w3;
}

// ---------------------------------------------------------------------------
// Launch
// ---------------------------------------------------------------------------
extern "C" void kernel_launch(void* const* d_in, const int* in_sizes, int n_in,
                              void* d_out, int out_size)
{
    const float* x         = (const float*)d_in[0];
    const float* Wq        = (const float*)d_in[1];
    const float* Wk        = (const float*)d_in[2];
    const float* Wv        = (const float*)d_in[3];
    const float* Wo        = (const float*)d_in[4];
    const float* rel_table = (const float*)d_in[5];
    const float* mask      = (const float*)d_in[6];
    float* out = (float*)d_out;

    float *pq, *pk, *pv, *pa, *pbias;
    cudaGetSymbolAddress((void**)&pq,    g_q);
    cudaGetSymbolAddress((void**)&pk,    g_k);
    cudaGetSymbolAddress((void**)&pv,    g_v);
    cudaGetSymbolAddress((void**)&pa,    g_attn);
    cudaGetSymbolAddress((void**)&pbias, g_bias_tbl);

    // 1) bias table
    bias_table_kernel<<<(BIAS_TBL_N + 255) / 256, 256>>>(rel_table, pbias);

    // 2) QKV projections
    dim3 ggrid(DIM / 64, MROWS / 128);
    gemm_kernel<<<ggrid, 256>>>(x, Wq, pq, MROWS, DIM, DIM);
    gemm_kernel<<<ggrid, 256>>>(x, Wk, pk, MROWS, DIM, DIM);
    gemm_kernel<<<ggrid, 256>>>(x, Wv, pv, MROWS, DIM, DIM);

    // 3) attention
    cudaFuncSetAttribute(attn_kernel, cudaFuncAttributeMaxDynamicSharedMemorySize,
                         ATTN_SMEM_BYTES);
    dim3 agrid(SEQ / 64, HEADS, BATCH);
    attn_kernel<<<agrid, 256, ATTN_SMEM_BYTES>>>(pq, pk, pv, mask, pbias, pa);

    // 4) output projection -> first output
    gemm_kernel<<<ggrid, 256>>>(pa, Wo, out, MROWS, DIM, DIM);

    // 5) position_bias -> second output
    if ((size_t)out_size >= OUT_ELEMS + PB_ELEMS) {
        pb_out_kernel<<<(unsigned)(PB_ELEMS / 4 / 256), 256>>>(pbias, out + OUT_ELEMS);
    }
}

// round 2
// speedup vs baseline: 2.0030x; 2.0030x over previous
#include <cuda_runtime.h>
#include <math.h>
#include <stdint.h>

// Problem constants
#define BATCH 2
#define SEQ   2048
#define DIM   1024
#define HEADS 16
#define DKV   64
#define MROWS (BATCH*SEQ)                          // 4096
#define OUT_ELEMS   ((size_t)MROWS*DIM)            // 4194304
#define PB_ELEMS    ((size_t)HEADS*SEQ*SEQ)        // 67108864
#define BIAS_TBL_N  (HEADS*4095)                   // 65520

// Scratch (device globals, no runtime allocation)
__device__ float g_q[MROWS*DIM];
__device__ float g_k[MROWS*DIM];
__device__ float g_v[MROWS*DIM];
__device__ float g_attn[MROWS*DIM];
__device__ float g_bias_tbl[BIAS_TBL_N];

// ---------------------------------------------------------------------------
// TF32 helpers
// ---------------------------------------------------------------------------
__device__ __forceinline__ uint32_t f2tf(float f) {
    uint32_t u;
    asm("cvt.rna.tf32.f32 %0, %1;" : "=r"(u) : "f"(f));
    return u;
}
// (hi, lo) split: a ~= hi + lo, both tf32-representable (stored as float bits)
__device__ __forceinline__ float2 split2(float f) {
    uint32_t h = f2tf(f);
    float hf = __uint_as_float(h);
    uint32_t l = f2tf(f - hf);
    return make_float2(hf, __uint_as_float(l));
}

__device__ __forceinline__ void mma8(float& d0, float& d1, float& d2, float& d3,
                                     uint32_t a0, uint32_t a1, uint32_t a2, uint32_t a3,
                                     uint32_t b0, uint32_t b1)
{
    asm volatile("mma.sync.aligned.m16n8k8.row.col.f32.tf32.tf32.f32 "
                 "{%0,%1,%2,%3}, {%4,%5,%6,%7}, {%8,%9}, {%0,%1,%2,%3};"
                 : "+f"(d0), "+f"(d1), "+f"(d2), "+f"(d3)
                 : "r"(a0), "r"(a1), "r"(a2), "r"(a3), "r"(b0), "r"(b1));
}

// ---------------------------------------------------------------------------
// Relative-position bias table: bias[h][rel + 2047], rel = k - q
// ---------------------------------------------------------------------------
__global__ void bias_table_kernel(const float* __restrict__ rel_table,
                                  float* __restrict__ bias)
{
    int i = blockIdx.x * blockDim.x + threadIdx.x;
    if (i >= BIAS_TBL_N) return;
    int h   = i / 4095;
    int rel = (i % 4095) - 2047;       // rel = k - q
    int n   = -rel;                    // q - k
    int ret = 0;
    if (n < 0) { ret = 16; n = -n; }
    int val;
    if (n < 8) {
        val = n;
    } else {
        float t = (logf((float)n / 8.0f) / 2.772588722239781f) * 8.0f;
        int it = (int)t;
        if (t - (float)it > 0.99995f) it += 1;
        val = 8 + it;
        if (val > 15) val = 15;
    }
    bias[i] = rel_table[(val + ret) * HEADS + h];
}

// ---------------------------------------------------------------------------
// Broadcast bias table into the position_bias output [H][S][S]
// ---------------------------------------------------------------------------
__global__ __launch_bounds__(256) void pb_out_kernel(const float* __restrict__ bias,
                                                     float* __restrict__ pb)
{
    size_t i = ((size_t)blockIdx.x * blockDim.x + threadIdx.x) * 4;
    int k = (int)(i & 2047);
    int q = (int)((i >> 11) & 2047);
    int h = (int)(i >> 22);
    const float* src = bias + h * 4095 + 2047 - q + k;
    float4 v = make_float4(src[0], src[1], src[2], src[3]);
    *(float4*)(pb + i) = v;
}

// ---------------------------------------------------------------------------
// 3xTF32 GEMM: C[M,N] = A[M,K] @ B[K,N].  BM=128 BN=64 BK=32, 256 threads.
// Warps 4(M) x 2(N): warp tile 32x32 = 2 mtiles x 4 ntiles of m16n8k8.
// smem holds (hi,lo) float2 per element; conflict-free fragment strides.
// ---------------------------------------------------------------------------
#define GA_STR 36   // float2 units per A row (128 rows)
#define GB_STR 72   // float2 units per B row (32 rows)
#define GEMM_SMEM_BYTES ((128*GA_STR + 32*GB_STR) * (int)sizeof(float2))

__global__ __launch_bounds__(256) void gemm_tf32(const float* __restrict__ A,
                                                 const float* __restrict__ B,
                                                 float* __restrict__ C,
                                                 int M, int N, int K)
{
    extern __shared__ float2 sm2[];
    float2* As = sm2;                    // [128][GA_STR]
    float2* Bs = sm2 + 128 * GA_STR;     // [32][GB_STR]

    const int tid  = threadIdx.x;
    const int lane = tid & 31;
    const int warp = tid >> 5;
    const int wm   = warp >> 1;          // 0..3
    const int wn   = warp & 1;           // 0..1
    const int l4   = lane >> 2;          // 0..7
    const int lc   = lane & 3;           // 0..3
    const int m0   = blockIdx.y * 128;
    const int n0   = blockIdx.x * 64;

    float acc[2][4][4];
#pragma unroll
    for (int mt = 0; mt < 2; mt++)
#pragma unroll
        for (int nt = 0; nt < 4; nt++)
#pragma unroll
            for (int j = 0; j < 4; j++) acc[mt][nt][j] = 0.f;

    const int ar = tid >> 1, ac = (tid & 1) * 16;   // A: 16 floats/thread
    const int br = tid >> 3, bc = (tid & 7) * 8;    // B: 8 floats/thread
    const float* Ap = A + (size_t)(m0 + ar) * K + ac;
    const float* Bp = B + (size_t)br * N + n0 + bc;

    for (int kt = 0; kt < K; kt += 32) {
        float4 av[4], bv[2];
#pragma unroll
        for (int j = 0; j < 4; j++) av[j] = *(const float4*)(Ap + 4 * j);
#pragma unroll
        for (int j = 0; j < 2; j++) bv[j] = *(const float4*)(Bp + 4 * j);
        Ap += 32;
        Bp += (size_t)32 * N;

        __syncthreads();
#pragma unroll
        for (int j = 0; j < 4; j++) {
            float2 s0 = split2(av[j].x), s1 = split2(av[j].y);
            float2 s2 = split2(av[j].z), s3 = split2(av[j].w);
            *(float4*)&As[ar * GA_STR + ac + 4 * j]     = make_float4(s0.x, s0.y, s1.x, s1.y);
            *(float4*)&As[ar * GA_STR + ac + 4 * j + 2] = make_float4(s2.x, s2.y, s3.x, s3.y);
        }
#pragma unroll
        for (int j = 0; j < 2; j++) {
            float2 s0 = split2(bv[j].x), s1 = split2(bv[j].y);
            float2 s2 = split2(bv[j].z), s3 = split2(bv[j].w);
            *(float4*)&Bs[br * GB_STR + bc + 4 * j]     = make_float4(s0.x, s0.y, s1.x, s1.y);
            *(float4*)&Bs[br * GB_STR + bc + 4 * j + 2] = make_float4(s2.x, s2.y, s3.x, s3.y);
        }
        __syncthreads();

#pragma unroll
        for (int s = 0; s < 4; s++) {
            const int kk = s * 8 + lc;
            uint32_t ah[2][4], al[2][4];
#pragma unroll
            for (int mt = 0; mt < 2; mt++) {
                int row = wm * 32 + mt * 16 + l4;
                float2 t;
                t = As[(row)     * GA_STR + kk];     ah[mt][0] = __float_as_uint(t.x); al[mt][0] = __float_as_uint(t.y);
                t = As[(row + 8) * GA_STR + kk];     ah[mt][1] = __float_as_uint(t.x); al[mt][1] = __float_as_uint(t.y);
                t = As[(row)     * GA_STR + kk + 4]; ah[mt][2] = __float_as_uint(t.x); al[mt][2] = __float_as_uint(t.y);
                t = As[(row + 8) * GA_STR + kk + 4]; ah[mt][3] = __float_as_uint(t.x); al[mt][3] = __float_as_uint(t.y);
            }
#pragma unroll
            for (int nt = 0; nt < 4; nt++) {
                int col = wn * 32 + nt * 8 + l4;
                float2 b0 = Bs[(kk)     * GB_STR + col];
                float2 b1 = Bs[(kk + 4) * GB_STR + col];
                uint32_t bh0 = __float_as_uint(b0.x), bl0 = __float_as_uint(b0.y);
                uint32_t bh1 = __float_as_uint(b1.x), bl1 = __float_as_uint(b1.y);
#pragma unroll
                for (int mt = 0; mt < 2; mt++) {
                    mma8(acc[mt][nt][0], acc[mt][nt][1], acc[mt][nt][2], acc[mt][nt][3],
                         ah[mt][0], ah[mt][1], ah[mt][2], ah[mt][3], bh0, bh1);
                    mma8(acc[mt][nt][0], acc[mt][nt][1], acc[mt][nt][2], acc[mt][nt][3],
                         ah[mt][0], ah[mt][1], ah[mt][2], ah[mt][3], bl0, bl1);
                    mma8(acc[mt][nt][0], acc[mt][nt][1], acc[mt][nt][2], acc[mt][nt][3],
                         al[mt][0], al[mt][1], al[mt][2], al[mt][3], bh0, bh1);
                }
            }
        }
    }

#pragma unroll
    for (int mt = 0; mt < 2; mt++) {
#pragma unroll
        for (int nt = 0; nt < 4; nt++) {
            int row = m0 + wm * 32 + mt * 16 + l4;
            int col = n0 + wn * 32 + nt * 8 + 2 * lc;
            *(float2*)&C[(size_t)(row)     * N + col] = make_float2(acc[mt][nt][0], acc[mt][nt][1]);
            *(float2*)&C[(size_t)(row + 8) * N + col] = make_float2(acc[mt][nt][2], acc[mt][nt][3]);
        }
    }
}

// ---------------------------------------------------------------------------
// Flash attention with tf32 mma. Block = 256 thr (8 warps), Q-tile 128 rows,
// K-tile 64 keys. QK^T uses 3xTF32 (Q frags hi/lo in regs, K hi/lo float2 in
// smem). PV uses plain TF32 (P, V rounded). Softmax in C-frag registers.
// ---------------------------------------------------------------------------
#define SS_STR 68   // floats per Ss row (128 rows)  -> a-frag pattern conflict-free
#define KK_STR 68   // float2 per K2 row (64 rows)   -> b-frag LDS.64 conflict-free
#define VV_STR 72   // floats per Vs row (64 rows)   -> b-frag pattern conflict-free
#define ATTN_SMEM_FLOATS (128*SS_STR + 64*KK_STR*2 + 64*VV_STR + 192 + 64)
#define ATTN_SMEM_BYTES  (ATTN_SMEM_FLOATS * (int)sizeof(float))

__global__ __launch_bounds__(256, 1) void attn_tf32(const float* __restrict__ Q,
                                                    const float* __restrict__ K,
                                                    const float* __restrict__ V,
                                                    const float* __restrict__ mask,
                                                    const float* __restrict__ bias,
                                                    float* __restrict__ O)
{
    extern __shared__ float smf[];
    float*  Ss = smf;                                    // [128][SS_STR] (Q raw, then P)
    float2* K2 = (float2*)(smf + 128 * SS_STR);          // [64][KK_STR] (hi,lo)
    float*  Vs = smf + 128 * SS_STR + 64 * KK_STR * 2;   // [64][VV_STR]
    float*  bw = Vs + 64 * VV_STR;                       // [191]
    float*  msk = bw + 192;                              // [64]

    const int tid  = threadIdx.x;
    const int lane = tid & 31;
    const int warp = tid >> 5;
    const int l4   = lane >> 2;
    const int lc   = lane & 3;
    const int b    = blockIdx.z;
    const int h    = blockIdx.y;
    const int q0   = blockIdx.x * 128;

    // ---- load Q tile raw into Ss ----
    {
        int r = tid >> 1, c0 = (tid & 1) * 32;
        const float* Qb = Q + ((size_t)(b * SEQ + q0 + r)) * DIM + h * DKV + c0;
#pragma unroll
        for (int j = 0; j < 8; j++)
            *(float4*)&Ss[r * SS_STR + c0 + 4 * j] = *(const float4*)(Qb + 4 * j);
    }
    __syncthreads();

    // ---- build Q fragments (hi/lo) in registers ----
    uint32_t qh[8][4], ql[8][4];
    const int r0 = warp * 16 + l4;
#pragma unroll
    for (int s = 0; s < 8; s++) {
        int kk = s * 8 + lc;
        float2 t;
        t = split2(Ss[(r0)     * SS_STR + kk]);     qh[s][0] = __float_as_uint(t.x); ql[s][0] = __float_as_uint(t.y);
        t = split2(Ss[(r0 + 8) * SS_STR + kk]);     qh[s][1] = __float_as_uint(t.x); ql[s][1] = __float_as_uint(t.y);
        t = split2(Ss[(r0)     * SS_STR + kk + 4]); qh[s][2] = __float_as_uint(t.x); ql[s][2] = __float_as_uint(t.y);
        t = split2(Ss[(r0 + 8) * SS_STR + kk + 4]); qh[s][3] = __float_as_uint(t.x); ql[s][3] = __float_as_uint(t.y);
    }

    float o[8][4];
#pragma unroll
    for (int dt = 0; dt < 8; dt++)
#pragma unroll
        for (int j = 0; j < 4; j++) o[dt][j] = 0.f;
    float mrow[2] = {-INFINITY, -INFINITY};
    float lrow[2] = {0.f, 0.f};

    const int relbase = h * 4095 + 2047 - q0 - 127;   // + k0 + t

    for (int k0 = 0; k0 < SEQ; k0 += 64) {
        __syncthreads();
        // ---- load K (hi/lo) and V (tf32) tiles ----
        {
            int r = tid >> 2, c = (tid & 3) * 16;
            const float* Kb = K + ((size_t)(b * SEQ + k0 + r)) * DIM + h * DKV + c;
            const float* Vb = V + ((size_t)(b * SEQ + k0 + r)) * DIM + h * DKV + c;
#pragma unroll
            for (int j = 0; j < 4; j++) {
                float4 kv = *(const float4*)(Kb + 4 * j);
                float2 s0 = split2(kv.x), s1 = split2(kv.y);
                float2 s2 = split2(kv.z), s3 = split2(kv.w);
                *(float4*)&K2[r * KK_STR + c + 4 * j]     = make_float4(s0.x, s0.y, s1.x, s1.y);
                *(float4*)&K2[r * KK_STR + c + 4 * j + 2] = make_float4(s2.x, s2.y, s3.x, s3.y);
                float4 vv = *(const float4*)(Vb + 4 * j);
                float4 vt = make_float4(__uint_as_float(f2tf(vv.x)), __uint_as_float(f2tf(vv.y)),
                                        __uint_as_float(f2tf(vv.z)), __uint_as_float(f2tf(vv.w)));
                *(float4*)&Vs[r * VV_STR + c + 4 * j] = vt;
            }
            if (tid < 191) bw[tid] = __ldg(&bias[relbase + k0 + tid]);
            if (tid < 64)  msk[tid] = mask[b * SEQ + k0 + tid];
        }
        __syncthreads();

        // ---- S = Q K^T (3xTF32) ----
        float sf[8][4];
#pragma unroll
        for (int nt = 0; nt < 8; nt++)
#pragma unroll
            for (int j = 0; j < 4; j++) sf[nt][j] = 0.f;

#pragma unroll
        for (int s = 0; s < 8; s++) {
            const int kk = s * 8 + lc;
#pragma unroll
            for (int nt = 0; nt < 8; nt++) {
                int key = nt * 8 + l4;
                float2 b0 = K2[key * KK_STR + kk];
                float2 b1 = K2[key * KK_STR + kk + 4];
                uint32_t bh0 = __float_as_uint(b0.x), bl0 = __float_as_uint(b0.y);
                uint32_t bh1 = __float_as_uint(b1.x), bl1 = __float_as_uint(b1.y);
                mma8(sf[nt][0], sf[nt][1], sf[nt][2], sf[nt][3],
                     qh[s][0], qh[s][1], qh[s][2], qh[s][3], bh0, bh1);
                mma8(sf[nt][0], sf[nt][1], sf[nt][2], sf[nt][3],
                     qh[s][0], qh[s][1], qh[s][2], qh[s][3], bl0, bl1);
                mma8(sf[nt][0], sf[nt][1], sf[nt][2], sf[nt][3],
                     ql[s][0], ql[s][1], ql[s][2], ql[s][3], bh0, bh1);
            }
        }

        // ---- bias + mask + online softmax (per C-frag row) ----
#pragma unroll
        for (int i = 0; i < 2; i++) {
            int qlcl = warp * 16 + l4 + 8 * i;
            float vmax = -INFINITY;
#pragma unroll
            for (int nt = 0; nt < 8; nt++) {
#pragma unroll
                for (int j = 0; j < 2; j++) {
                    int klcl = nt * 8 + 2 * lc + j;
                    float v = sf[nt][2 * i + j] + bw[klcl - qlcl + 127] + msk[klcl];
                    sf[nt][2 * i + j] = v;
                    vmax = fmaxf(vmax, v);
                }
            }
            vmax = fmaxf(vmax, __shfl_xor_sync(0xffffffffu, vmax, 1));
            vmax = fmaxf(vmax, __shfl_xor_sync(0xffffffffu, vmax, 2));
            float mnew = fmaxf(mrow[i], vmax);
            float corr = __expf(mrow[i] - mnew);
            mrow[i] = mnew;
            float rsum = 0.f;
#pragma unroll
            for (int nt = 0; nt < 8; nt++) {
#pragma unroll
                for (int j = 0; j < 2; j++) {
                    float p = __expf(sf[nt][2 * i + j] - mnew);
                    sf[nt][2 * i + j] = p;
                    rsum += p;
                }
            }
            rsum += __shfl_xor_sync(0xffffffffu, rsum, 1);
            rsum += __shfl_xor_sync(0xffffffffu, rsum, 2);
            lrow[i] = lrow[i] * corr + rsum;
#pragma unroll
            for (int dt = 0; dt < 8; dt++) {
                o[dt][2 * i]     *= corr;
                o[dt][2 * i + 1] *= corr;
            }
        }

        // ---- write P (tf32) to Ss ----
#pragma unroll
        for (int nt = 0; nt < 8; nt++) {
#pragma unroll
            for (int idx = 0; idx < 4; idx++) {
                int row = warp * 16 + l4 + 8 * (idx >> 1);
                int col = nt * 8 + 2 * lc + (idx & 1);
                Ss[row * SS_STR + col] = __uint_as_float(f2tf(sf[nt][idx]));
            }
        }
        __syncthreads();

        // ---- O += P V (plain TF32) ----
#pragma unroll
        for (int s = 0; s < 8; s++) {
            const int kk = s * 8 + lc;
            uint32_t pa0 = __float_as_uint(Ss[(r0)     * SS_STR + kk]);
            uint32_t pa1 = __float_as_uint(Ss[(r0 + 8) * SS_STR + kk]);
            uint32_t pa2 = __float_as_uint(Ss[(r0)     * SS_STR + kk + 4]);
            uint32_t pa3 = __float_as_uint(Ss[(r0 + 8) * SS_STR + kk + 4]);
#pragma unroll
            for (int dt = 0; dt < 8; dt++) {
                int dc = dt * 8 + l4;
                uint32_t vb0 = __float_as_uint(Vs[(kk)     * VV_STR + dc]);
                uint32_t vb1 = __float_as_uint(Vs[(kk + 4) * VV_STR + dc]);
                mma8(o[dt][0], o[dt][1], o[dt][2], o[dt][3],
                     pa0, pa1, pa2, pa3, vb0, vb1);
            }
        }
    }

    // ---- epilogue ----
#pragma unroll
    for (int i = 0; i < 2; i++) {
        float inv = 1.0f / lrow[i];
        size_t base = ((size_t)(b * SEQ + q0 + warp * 16 + l4 + 8 * i)) * DIM + h * DKV;
#pragma unroll
        for (int dt = 0; dt < 8; dt++) {
            *(float2*)&O[base + dt * 8 + 2 * lc] =
                make_float2(o[dt][2 * i] * inv, o[dt][2 * i + 1] * inv);
        }
    }
}

// ---------------------------------------------------------------------------
// Launch
// ---------------------------------------------------------------------------
extern "C" void kernel_launch(void* const* d_in, const int* in_sizes, int n_in,
                              void* d_out, int out_size)
{
    const float* x         = (const float*)d_in[0];
    const float* Wq        = (const float*)d_in[1];
    const float* Wk        = (const float*)d_in[2];
    const float* Wv        = (const float*)d_in[3];
    const float* Wo        = (const float*)d_in[4];
    const float* rel_table = (const float*)d_in[5];
    const float* mask      = (const float*)d_in[6];
    float* out = (float*)d_out;

    float *pq, *pk, *pv, *pa, *pbias;
    cudaGetSymbolAddress((void**)&pq,    g_q);
    cudaGetSymbolAddress((void**)&pk,    g_k);
    cudaGetSymbolAddress((void**)&pv,    g_v);
    cudaGetSymbolAddress((void**)&pa,    g_attn);
    cudaGetSymbolAddress((void**)&pbias, g_bias_tbl);

    cudaFuncSetAttribute(gemm_tf32, cudaFuncAttributeMaxDynamicSharedMemorySize,
                         GEMM_SMEM_BYTES);
    cudaFuncSetAttribute(attn_tf32, cudaFuncAttributeMaxDynamicSharedMemorySize,
                         ATTN_SMEM_BYTES);

    // 1) bias table
    bias_table_kernel<<<(BIAS_TBL_N + 255) / 256, 256>>>(rel_table, pbias);

    // 2) QKV projections (3xTF32 tensor-core GEMMs)
    dim3 ggrid(DIM / 64, MROWS / 128);
    gemm_tf32<<<ggrid, 256, GEMM_SMEM_BYTES>>>(x, Wq, pq, MROWS, DIM, DIM);
    gemm_tf32<<<ggrid, 256, GEMM_SMEM_BYTES>>>(x, Wk, pk, MROWS, DIM, DIM);
    gemm_tf32<<<ggrid, 256, GEMM_SMEM_BYTES>>>(x, Wv, pv, MROWS, DIM, DIM);

    // 3) flash attention (tensor-core)
    dim3 agrid(SEQ / 128, HEADS, BATCH);
    attn_tf32<<<agrid, 256, ATTN_SMEM_BYTES>>>(pq, pk, pv, mask, pbias, pa);

    // 4) output projection -> first output
    gemm_tf32<<<ggrid, 256, GEMM_SMEM_BYTES>>>(pa, Wo, out, MROWS, DIM, DIM);

    // 5) position_bias -> second output
    if ((size_t)out_size >= OUT_ELEMS + PB_ELEMS) {
        pb_out_kernel<<<(unsigned)(PB_ELEMS / 4 / 256), 256>>>(pbias, out + OUT_ELEMS);
    }
}

// round 5
// speedup vs baseline: 2.4986x; 1.2474x over previous
#include <cuda_runtime.h>
#include <math.h>
#include <stdint.h>

// Problem constants
#define BATCH 2
#define SEQ   2048
#define DIM   1024
#define HEADS 16
#define DKV   64
#define MROWS (BATCH*SEQ)                          // 4096
#define OUT_ELEMS   ((size_t)MROWS*DIM)            // 4194304
#define PB_ELEMS    ((size_t)HEADS*SEQ*SEQ)        // 67108864
#define BIAS_TBL_N  (HEADS*4095)                   // 65520

// Scratch (device globals, no runtime allocation)
__device__ float g_q[MROWS*DIM];
__device__ float g_k[MROWS*DIM];
__device__ float g_v[MROWS*DIM];
__device__ float g_attn[MROWS*DIM];
__device__ float g_bias_tbl[BIAS_TBL_N];

// ---------------------------------------------------------------------------
// TF32 helpers (verified contract from round 2)
// ---------------------------------------------------------------------------
__device__ __forceinline__ uint32_t f2tf(float f) {
    uint32_t u;
    asm("cvt.rna.tf32.f32 %0, %1;" : "=r"(u) : "f"(f));
    return u;
}
// (hi, lo) split: a ~= hi + lo, both tf32-representable (stored as float bits)
__device__ __forceinline__ float2 split2(float f) {
    uint32_t h = f2tf(f);
    float hf = __uint_as_float(h);
    uint32_t l = f2tf(f - hf);
    return make_float2(hf, __uint_as_float(l));
}

__device__ __forceinline__ void mma8(float& d0, float& d1, float& d2, float& d3,
                                     uint32_t a0, uint32_t a1, uint32_t a2, uint32_t a3,
                                     uint32_t b0, uint32_t b1)
{
    asm volatile("mma.sync.aligned.m16n8k8.row.col.f32.tf32.tf32.f32 "
                 "{%0,%1,%2,%3}, {%4,%5,%6,%7}, {%8,%9}, {%0,%1,%2,%3};"
                 : "+f"(d0), "+f"(d1), "+f"(d2), "+f"(d3)
                 : "r"(a0), "r"(a1), "r"(a2), "r"(a3), "r"(b0), "r"(b1));
}

// ---------------------------------------------------------------------------
// Relative-position bias table: bias[h][rel + 2047], rel = k - q
// ---------------------------------------------------------------------------
__global__ void bias_table_kernel(const float* __restrict__ rel_table,
                                  float* __restrict__ bias)
{
    int i = blockIdx.x * blockDim.x + threadIdx.x;
    if (i >= BIAS_TBL_N) return;
    int h   = i / 4095;
    int rel = (i % 4095) - 2047;       // rel = k - q
    int n   = -rel;                    // q - k
    int ret = 0;
    if (n < 0) { ret = 16; n = -n; }
    int val;
    if (n < 8) {
        val = n;
    } else {
        float t = (logf((float)n / 8.0f) / 2.772588722239781f) * 8.0f;
        int it = (int)t;
        if (t - (float)it > 0.99995f) it += 1;
        val = 8 + it;
        if (val > 15) val = 15;
    }
    bias[i] = rel_table[(val + ret) * HEADS + h];
}

// ---------------------------------------------------------------------------
// Broadcast bias table into the position_bias output [H][S][S]
// ---------------------------------------------------------------------------
__global__ __launch_bounds__(256) void pb_out_kernel(const float* __restrict__ bias,
                                                     float* __restrict__ pb)
{
    size_t i = ((size_t)blockIdx.x * blockDim.x + threadIdx.x) * 4;
    int k = (int)(i & 2047);
    int q = (int)((i >> 11) & 2047);
    int h = (int)(i >> 22);
    const float* src = bias + h * 4095 + 2047 - q + k;
    float4 v = make_float4(src[0], src[1], src[2], src[3]);
    *(float4*)(pb + i) = v;
}

// ---------------------------------------------------------------------------
// 3xTF32 GEMM (VERIFIED round-2 body): C = A[M,K] @ B[K,N].
// BM=128 BN=64 BK=32, 256 threads. blockIdx.z selects (B,C) pair (Q,K fusion).
// ---------------------------------------------------------------------------
#define GA_STR 36   // float2 units per A row (128 rows)
#define GB_STR 72   // float2 units per B row (32 rows)
#define GEMM_SMEM_BYTES ((128*GA_STR + 32*GB_STR) * (int)sizeof(float2))

__global__ __launch_bounds__(256) void gemm_tf32(const float* __restrict__ A,
                                                 const float* __restrict__ B0,
                                                 const float* __restrict__ B1,
                                                 float* __restrict__ C0,
                                                 float* __restrict__ C1,
                                                 int M, int N, int K)
{
    const float* B = (blockIdx.z == 0) ? B0 : B1;
    float*       C = (blockIdx.z == 0) ? C0 : C1;

    extern __shared__ float2 sm2[];
    float2* As = sm2;                    // [128][GA_STR]
    float2* Bs = sm2 + 128 * GA_STR;     // [32][GB_STR]

    const int tid  = threadIdx.x;
    const int lane = tid & 31;
    const int warp = tid >> 5;
    const int wm   = warp >> 1;          // 0..3
    const int wn   = warp & 1;           // 0..1
    const int l4   = lane >> 2;          // 0..7
    const int lc   = lane & 3;           // 0..3
    const int m0   = blockIdx.y * 128;
    const int n0   = blockIdx.x * 64;

    float acc[2][4][4];
#pragma unroll
    for (int mt = 0; mt < 2; mt++)
#pragma unroll
        for (int nt = 0; nt < 4; nt++)
#pragma unroll
            for (int j = 0; j < 4; j++) acc[mt][nt][j] = 0.f;

    const int ar = tid >> 1, ac = (tid & 1) * 16;   // A: 16 floats/thread
    const int br = tid >> 3, bc = (tid & 7) * 8;    // B: 8 floats/thread
    const float* Ap = A + (size_t)(m0 + ar) * K + ac;
    const float* Bp = B + (size_t)br * N + n0 + bc;

    for (int kt = 0; kt < K; kt += 32) {
        float4 av[4], bv[2];
#pragma unroll
        for (int j = 0; j < 4; j++) av[j] = *(const float4*)(Ap + 4 * j);
#pragma unroll
        for (int j = 0; j < 2; j++) bv[j] = *(const float4*)(Bp + 4 * j);
        Ap += 32;
        Bp += (size_t)32 * N;

        __syncthreads();
#pragma unroll
        for (int j = 0; j < 4; j++) {
            float2 s0 = split2(av[j].x), s1 = split2(av[j].y);
            float2 s2 = split2(av[j].z), s3 = split2(av[j].w);
            *(float4*)&As[ar * GA_STR + ac + 4 * j]     = make_float4(s0.x, s0.y, s1.x, s1.y);
            *(float4*)&As[ar * GA_STR + ac + 4 * j + 2] = make_float4(s2.x, s2.y, s3.x, s3.y);
        }
#pragma unroll
        for (int j = 0; j < 2; j++) {
            float2 s0 = split2(bv[j].x), s1 = split2(bv[j].y);
            float2 s2 = split2(bv[j].z), s3 = split2(bv[j].w);
            *(float4*)&Bs[br * GB_STR + bc + 4 * j]     = make_float4(s0.x, s0.y, s1.x, s1.y);
            *(float4*)&Bs[br * GB_STR + bc + 4 * j + 2] = make_float4(s2.x, s2.y, s3.x, s3.y);
        }
        __syncthreads();

#pragma unroll
        for (int s = 0; s < 4; s++) {
            const int kk = s * 8 + lc;
            uint32_t ah[2][4], al[2][4];
#pragma unroll
            for (int mt = 0; mt < 2; mt++) {
                int row = wm * 32 + mt * 16 + l4;
                float2 t;
                t = As[(row)     * GA_STR + kk];     ah[mt][0] = __float_as_uint(t.x); al[mt][0] = __float_as_uint(t.y);
                t = As[(row + 8) * GA_STR + kk];     ah[mt][1] = __float_as_uint(t.x); al[mt][1] = __float_as_uint(t.y);
                t = As[(row)     * GA_STR + kk + 4]; ah[mt][2] = __float_as_uint(t.x); al[mt][2] = __float_as_uint(t.y);
                t = As[(row + 8) * GA_STR + kk + 4]; ah[mt][3] = __float_as_uint(t.x); al[mt][3] = __float_as_uint(t.y);
            }
#pragma unroll
            for (int nt = 0; nt < 4; nt++) {
                int col = wn * 32 + nt * 8 + l4;
                float2 b0 = Bs[(kk)     * GB_STR + col];
                float2 b1 = Bs[(kk + 4) * GB_STR + col];
                uint32_t bh0 = __float_as_uint(b0.x), bl0 = __float_as_uint(b0.y);
                uint32_t bh1 = __float_as_uint(b1.x), bl1 = __float_as_uint(b1.y);
#pragma unroll
                for (int mt = 0; mt < 2; mt++) {
                    mma8(acc[mt][nt][0], acc[mt][nt][1], acc[mt][nt][2], acc[mt][nt][3],
                         ah[mt][0], ah[mt][1], ah[mt][2], ah[mt][3], bh0, bh1);
                    mma8(acc[mt][nt][0], acc[mt][nt][1], acc[mt][nt][2], acc[mt][nt][3],
                         ah[mt][0], ah[mt][1], ah[mt][2], ah[mt][3], bl0, bl1);
                    mma8(acc[mt][nt][0], acc[mt][nt][1], acc[mt][nt][2], acc[mt][nt][3],
                         al[mt][0], al[mt][1], al[mt][2], al[mt][3], bh0, bh1);
                }
            }
        }
    }

#pragma unroll
    for (int mt = 0; mt < 2; mt++) {
#pragma unroll
        for (int nt = 0; nt < 4; nt++) {
            int row = m0 + wm * 32 + mt * 16 + l4;
            int col = n0 + wn * 32 + nt * 8 + 2 * lc;
            *(float2*)&C[(size_t)(row)     * N + col] = make_float2(acc[mt][nt][0], acc[mt][nt][1]);
            *(float2*)&C[(size_t)(row + 8) * N + col] = make_float2(acc[mt][nt][2], acc[mt][nt][3]);
        }
    }
}

// ---------------------------------------------------------------------------
// Plain TF32 GEMM (1 MMA per k8): for V-projection and O-projection.
// Same tiling/fragment geometry as the verified 3-term kernel; smem holds a
// single tf32 float per element (half the LDS bytes, 1/3 the MMAs).
// ---------------------------------------------------------------------------
#define A1_STR 36
#define B1_STR 68
#define GEMM1_SMEM_BYTES ((128*A1_STR + 32*B1_STR) * 4)

__global__ __launch_bounds__(256) void gemm_tf32_1t(const float* __restrict__ A,
                                                    const float* __restrict__ B,
                                                    float* __restrict__ C,
                                                    int M, int N, int K)
{
    extern __shared__ float sm1[];
    float* As = sm1;                   // [128][A1_STR]
    float* Bs = sm1 + 128 * A1_STR;    // [32][B1_STR]

    const int tid  = threadIdx.x;
    const int lane = tid & 31;
    const int warp = tid >> 5;
    const int wm   = warp >> 1;
    const int wn   = warp & 1;
    const int l4   = lane >> 2;
    const int lc   = lane & 3;
    const int m0   = blockIdx.y * 128;
    const int n0   = blockIdx.x * 64;

    float acc[2][4][4];
#pragma unroll
    for (int mt = 0; mt < 2; mt++)
#pragma unroll
        for (int nt = 0; nt < 4; nt++)
#pragma unroll
            for (int j = 0; j < 4; j++) acc[mt][nt][j] = 0.f;

    const int ar = tid >> 1, ac = (tid & 1) * 16;
    const int br = tid >> 3, bc = (tid & 7) * 8;
    const float* Ap = A + (size_t)(m0 + ar) * K + ac;
    const float* Bp = B + (size_t)br * N + n0 + bc;

    for (int kt = 0; kt < K; kt += 32) {
        float4 av[4], bv[2];
#pragma unroll
        for (int j = 0; j < 4; j++) av[j] = *(const float4*)(Ap + 4 * j);
#pragma unroll
        for (int j = 0; j < 2; j++) bv[j] = *(const float4*)(Bp + 4 * j);
        Ap += 32;
        Bp += (size_t)32 * N;

        __syncthreads();
#pragma unroll
        for (int j = 0; j < 4; j++) {
            float4 t = make_float4(__uint_as_float(f2tf(av[j].x)), __uint_as_float(f2tf(av[j].y)),
                                   __uint_as_float(f2tf(av[j].z)), __uint_as_float(f2tf(av[j].w)));
            *(float4*)&As[ar * A1_STR + ac + 4 * j] = t;
        }
#pragma unroll
        for (int j = 0; j < 2; j++) {
            float4 t = make_float4(__uint_as_float(f2tf(bv[j].x)), __uint_as_float(f2tf(bv[j].y)),
                                   __uint_as_float(f2tf(bv[j].z)), __uint_as_float(f2tf(bv[j].w)));
            *(float4*)&Bs[br * B1_STR + bc + 4 * j] = t;
        }
        __syncthreads();

#pragma unroll
        for (int s = 0; s < 4; s++) {
            const int kk = s * 8 + lc;
            uint32_t a[2][4];
#pragma unroll
            for (int mt = 0; mt < 2; mt++) {
                int row = wm * 32 + mt * 16 + l4;
                a[mt][0] = __float_as_uint(As[(row)     * A1_STR + kk]);
                a[mt][1] = __float_as_uint(As[(row + 8) * A1_STR + kk]);
                a[mt][2] = __float_as_uint(As[(row)     * A1_STR + kk + 4]);
                a[mt][3] = __float_as_uint(As[(row + 8) * A1_STR + kk + 4]);
            }
#pragma unroll
            for (int nt = 0; nt < 4; nt++) {
                int col = wn * 32 + nt * 8 + l4;
                uint32_t b0 = __float_as_uint(Bs[(kk)     * B1_STR + col]);
                uint32_t b1 = __float_as_uint(Bs[(kk + 4) * B1_STR + col]);
#pragma unroll
                for (int mt = 0; mt < 2; mt++) {
                    mma8(acc[mt][nt][0], acc[mt][nt][1], acc[mt][nt][2], acc[mt][nt][3],
                         a[mt][0], a[mt][1], a[mt][2], a[mt][3], b0, b1);
                }
            }
        }
    }

#pragma unroll
    for (int mt = 0; mt < 2; mt++) {
#pragma unroll
        for (int nt = 0; nt < 4; nt++) {
            int row = m0 + wm * 32 + mt * 16 + l4;
            int col = n0 + wn * 32 + nt * 8 + 2 * lc;
            *(float2*)&C[(size_t)(row)     * N + col] = make_float2(acc[mt][nt][0], acc[mt][nt][1]);
            *(float2*)&C[(size_t)(row + 8) * N + col] = make_float2(acc[mt][nt][2], acc[mt][nt][3]);
        }
    }
}

// ---------------------------------------------------------------------------
// Flash attention (VERIFIED round-2 body, unchanged). Block = 256 thr,
// Q-tile 128, K-tile 64. QK^T 3xTF32, PV plain TF32.
// ---------------------------------------------------------------------------
#define SS_STR 68
#define KK_STR 68
#define VV_STR 72
#define ATTN_SMEM_FLOATS (128*SS_STR + 64*KK_STR*2 + 64*VV_STR + 192 + 64)
#define ATTN_SMEM_BYTES  (ATTN_SMEM_FLOATS * (int)sizeof(float))

__global__ __launch_bounds__(256, 1) void attn_tf32(const float* __restrict__ Q,
                                                    const float* __restrict__ K,
                                                    const float* __restrict__ V,
                                                    const float* __restrict__ mask,
                                                    const float* __restrict__ bias,
                                                    float* __restrict__ O)
{
    extern __shared__ float smf[];
    float*  Ss = smf;                                    // [128][SS_STR]
    float2* K2 = (float2*)(smf + 128 * SS_STR);          // [64][KK_STR]
    float*  Vs = smf + 128 * SS_STR + 64 * KK_STR * 2;   // [64][VV_STR]
    float*  bw = Vs + 64 * VV_STR;                       // [191]
    float*  msk = bw + 192;                              // [64]

    const int tid  = threadIdx.x;
    const int lane = tid & 31;
    const int warp = tid >> 5;
    const int l4   = lane >> 2;
    const int lc   = lane & 3;
    const int b    = blockIdx.z;
    const int h    = blockIdx.y;
    const int q0   = blockIdx.x * 128;

    {
        int r = tid >> 1, c0 = (tid & 1) * 32;
        const float* Qb = Q + ((size_t)(b * SEQ + q0 + r)) * DIM + h * DKV + c0;
#pragma unroll
        for (int j = 0; j < 8; j++)
            *(float4*)&Ss[r * SS_STR + c0 + 4 * j] = *(const float4*)(Qb + 4 * j);
    }
    __syncthreads();

    uint32_t qh[8][4], ql[8][4];
    const int r0 = warp * 16 + l4;
#pragma unroll
    for (int s = 0; s < 8; s++) {
        int kk = s * 8 + lc;
        float2 t;
        t = split2(Ss[(r0)     * SS_STR + kk]);     qh[s][0] = __float_as_uint(t.x); ql[s][0] = __float_as_uint(t.y);
        t = split2(Ss[(r0 + 8) * SS_STR + kk]);     qh[s][1] = __float_as_uint(t.x); ql[s][1] = __float_as_uint(t.y);
        t = split2(Ss[(r0)     * SS_STR + kk + 4]); qh[s][2] = __float_as_uint(t.x); ql[s][2] = __float_as_uint(t.y);
        t = split2(Ss[(r0 + 8) * SS_STR + kk + 4]); qh[s][3] = __float_as_uint(t.x); ql[s][3] = __float_as_uint(t.y);
    }

    float o[8][4];
#pragma unroll
    for (int dt = 0; dt < 8; dt++)
#pragma unroll
        for (int j = 0; j < 4; j++) o[dt][j] = 0.f;
    float mrow[2] = {-INFINITY, -INFINITY};
    float lrow[2] = {0.f, 0.f};

    const int relbase = h * 4095 + 2047 - q0 - 127;

    for (int k0 = 0; k0 < SEQ; k0 += 64) {
        __syncthreads();
        {
            int r = tid >> 2, c = (tid & 3) * 16;
            const float* Kb = K + ((size_t)(b * SEQ + k0 + r)) * DIM + h * DKV + c;
            const float* Vb = V + ((size_t)(b * SEQ + k0 + r)) * DIM + h * DKV + c;
#pragma unroll
            for (int j = 0; j < 4; j++) {
                float4 kv = *(const float4*)(Kb + 4 * j);
                float2 s0 = split2(kv.x), s1 = split2(kv.y);
                float2 s2 = split2(kv.z), s3 = split2(kv.w);
                *(float4*)&K2[r * KK_STR + c + 4 * j]     = make_float4(s0.x, s0.y, s1.x, s1.y);
                *(float4*)&K2[r * KK_STR + c + 4 * j + 2] = make_float4(s2.x, s2.y, s3.x, s3.y);
                float4 vv = *(const float4*)(Vb + 4 * j);
                float4 vt = make_float4(__uint_as_float(f2tf(vv.x)), __uint_as_float(f2tf(vv.y)),
                                        __uint_as_float(f2tf(vv.z)), __uint_as_float(f2tf(vv.w)));
                *(float4*)&Vs[r * VV_STR + c + 4 * j] = vt;
            }
            if (tid < 191) bw[tid] = __ldg(&bias[relbase + k0 + tid]);
            if (tid < 64)  msk[tid] = mask[b * SEQ + k0 + tid];
        }
        __syncthreads();

        float sf[8][4];
#pragma unroll
        for (int nt = 0; nt < 8; nt++)
#pragma unroll
            for (int j = 0; j < 4; j++) sf[nt][j] = 0.f;

#pragma unroll
        for (int s = 0; s < 8; s++) {
            const int kk = s * 8 + lc;
#pragma unroll
            for (int nt = 0; nt < 8; nt++) {
                int key = nt * 8 + l4;
                float2 b0 = K2[key * KK_STR + kk];
                float2 b1 = K2[key * KK_STR + kk + 4];
                uint32_t bh0 = __float_as_uint(b0.x), bl0 = __float_as_uint(b0.y);
                uint32_t bh1 = __float_as_uint(b1.x), bl1 = __float_as_uint(b1.y);
                mma8(sf[nt][0], sf[nt][1], sf[nt][2], sf[nt][3],
                     qh[s][0], qh[s][1], qh[s][2], qh[s][3], bh0, bh1);
                mma8(sf[nt][0], sf[nt][1], sf[nt][2], sf[nt][3],
                     qh[s][0], qh[s][1], qh[s][2], qh[s][3], bl0, bl1);
                mma8(sf[nt][0], sf[nt][1], sf[nt][2], sf[nt][3],
                     ql[s][0], ql[s][1], ql[s][2], ql[s][3], bh0, bh1);
            }
        }

#pragma unroll
        for (int i = 0; i < 2; i++) {
            int qlcl = warp * 16 + l4 + 8 * i;
            float vmax = -INFINITY;
#pragma unroll
            for (int nt = 0; nt < 8; nt++) {
#pragma unroll
                for (int j = 0; j < 2; j++) {
                    int klcl = nt * 8 + 2 * lc + j;
                    float v = sf[nt][2 * i + j] + bw[klcl - qlcl + 127] + msk[klcl];
                    sf[nt][2 * i + j] = v;
                    vmax = fmaxf(vmax, v);
                }
            }
            vmax = fmaxf(vmax, __shfl_xor_sync(0xffffffffu, vmax, 1));
            vmax = fmaxf(vmax, __shfl_xor_sync(0xffffffffu, vmax, 2));
            float mnew = fmaxf(mrow[i], vmax);
            float corr = __expf(mrow[i] - mnew);
            mrow[i] = mnew;
            float rsum = 0.f;
#pragma unroll
            for (int nt = 0; nt < 8; nt++) {
#pragma unroll
                for (int j = 0; j < 2; j++) {
                    float p = __expf(sf[nt][2 * i + j] - mnew);
                    sf[nt][2 * i + j] = p;
                    rsum += p;
                }
            }
            rsum += __shfl_xor_sync(0xffffffffu, rsum, 1);
            rsum += __shfl_xor_sync(0xffffffffu, rsum, 2);
            lrow[i] = lrow[i] * corr + rsum;
#pragma unroll
            for (int dt = 0; dt < 8; dt++) {
                o[dt][2 * i]     *= corr;
                o[dt][2 * i + 1] *= corr;
            }
        }

#pragma unroll
        for (int nt = 0; nt < 8; nt++) {
#pragma unroll
            for (int idx = 0; idx < 4; idx++) {
                int row = warp * 16 + l4 + 8 * (idx >> 1);
                int col = nt * 8 + 2 * lc + (idx & 1);
                Ss[row * SS_STR + col] = __uint_as_float(f2tf(sf[nt][idx]));
            }
        }
        __syncthreads();

#pragma unroll
        for (int s = 0; s < 8; s++) {
            const int kk = s * 8 + lc;
            uint32_t pa0 = __float_as_uint(Ss[(r0)     * SS_STR + kk]);
            uint32_t pa1 = __float_as_uint(Ss[(r0 + 8) * SS_STR + kk]);
            uint32_t pa2 = __float_as_uint(Ss[(r0)     * SS_STR + kk + 4]);
            uint32_t pa3 = __float_as_uint(Ss[(r0 + 8) * SS_STR + kk + 4]);
#pragma unroll
            for (int dt = 0; dt < 8; dt++) {
                int dc = dt * 8 + l4;
                uint32_t vb0 = __float_as_uint(Vs[(kk)     * VV_STR + dc]);
                uint32_t vb1 = __float_as_uint(Vs[(kk + 4) * VV_STR + dc]);
                mma8(o[dt][0], o[dt][1], o[dt][2], o[dt][3],
                     pa0, pa1, pa2, pa3, vb0, vb1);
            }
        }
    }

#pragma unroll
    for (int i = 0; i < 2; i++) {
        float inv = 1.0f / lrow[i];
        size_t base = ((size_t)(b * SEQ + q0 + warp * 16 + l4 + 8 * i)) * DIM + h * DKV;
#pragma unroll
        for (int dt = 0; dt < 8; dt++) {
            *(float2*)&O[base + dt * 8 + 2 * lc] =
                make_float2(o[dt][2 * i] * inv, o[dt][2 * i + 1] * inv);
        }
    }
}

// ---------------------------------------------------------------------------
// Launch
// ---------------------------------------------------------------------------
extern "C" void kernel_launch(void* const* d_in, const int* in_sizes, int n_in,
                              void* d_out, int out_size)
{
    const float* x         = (const float*)d_in[0];
    const float* Wq        = (const float*)d_in[1];
    const float* Wk        = (const float*)d_in[2];
    const float* Wv        = (const float*)d_in[3];
    const float* Wo        = (const float*)d_in[4];
    const float* rel_table = (const float*)d_in[5];
    const float* mask      = (const float*)d_in[6];
    float* out = (float*)d_out;

    float *pq, *pk, *pv, *pa, *pbias;
    cudaGetSymbolAddress((void**)&pq,    g_q);
    cudaGetSymbolAddress((void**)&pk,    g_k);
    cudaGetSymbolAddress((void**)&pv,    g_v);
    cudaGetSymbolAddress((void**)&pa,    g_attn);
    cudaGetSymbolAddress((void**)&pbias, g_bias_tbl);

    cudaFuncSetAttribute(gemm_tf32, cudaFuncAttributeMaxDynamicSharedMemorySize,
                         GEMM_SMEM_BYTES);
    cudaFuncSetAttribute(gemm_tf32_1t, cudaFuncAttributeMaxDynamicSharedMemorySize,
                         GEMM1_SMEM_BYTES);
    cudaFuncSetAttribute(attn_tf32, cudaFuncAttributeMaxDynamicSharedMemorySize,
                         ATTN_SMEM_BYTES);

    // 1) bias table
    bias_table_kernel<<<(BIAS_TBL_N + 255) / 256, 256>>>(rel_table, pbias);

    // 2) Q,K projections (3-term, fused launch) + V projection (1-term)
    dim3 qkgrid(DIM / 64, MROWS / 128, 2);
    gemm_tf32<<<qkgrid, 256, GEMM_SMEM_BYTES>>>(x, Wq, Wk, pq, pk, MROWS, DIM, DIM);
    dim3 vgrid(DIM / 64, MROWS / 128);
    gemm_tf32_1t<<<vgrid, 256, GEMM1_SMEM_BYTES>>>(x, Wv, pv, MROWS, DIM, DIM);

    // 3) flash attention
    dim3 agrid(SEQ / 128, HEADS, BATCH);
    attn_tf32<<<agrid, 256, ATTN_SMEM_BYTES>>>(pq, pk, pv, mask, pbias, pa);

    // 4) output projection (1-term) -> first output
    gemm_tf32_1t<<<vgrid, 256, GEMM1_SMEM_BYTES>>>(pa, Wo, out, MROWS, DIM, DIM);

    // 5) position_bias -> second output
    if ((size_t)out_size >= OUT_ELEMS + PB_ELEMS) {
        pb_out_kernel<<<(unsigned)(PB_ELEMS / 4 / 256), 256>>>(pbias, out + OUT_ELEMS);
    }
}